// round 5
// baseline (speedup 1.0000x reference)
#include <cuda_runtime.h>
#include <cuda_bf16.h>
#include <cstdint>

#define BATCH 1024
#define NN    8192
#define NB    8
#define TOTAL_IN 512

// Fragment-order scratch (bf16), filled by prep kernel.
// xfrag : [64 mtiles][32 ks][32 lanes] uint4 (a0..a3)                 = 1 MB
// wfrag2: [1024 ntiles][16 t][32 lanes] uint4 (b0e,b1e,b0o,b1o)       = 8 MB
__device__ uint4 g_xfrag[64 * 32 * 32];
__device__ uint4 g_wfrag2[1024 * 16 * 32];

__device__ __forceinline__ uint32_t pack_bf2(float lo, float hi) {
    __nv_bfloat162 h = __floats2bfloat162_rn(lo, hi);
    return *reinterpret_cast<uint32_t*>(&h);
}

// ---------------- prep: permute into mma fragment order ----------------
__global__ __launch_bounds__(256)
void prep_kernel(const float* __restrict__ x, const float* __restrict__ w) {
    const int NXF  = 64 * 32 * 32;        // 65536
    const int NWF2 = 1024 * 16 * 32;      // 524288
    int i = blockIdx.x * blockDim.x + threadIdx.x;
    if (i < NXF) {
        int lane = i & 31, ks = (i >> 5) & 31, mt = i >> 10;
        int k = ks >> 2, s = ks & 3, g = lane >> 2, q = lane & 3;
        int kk = k * 64 + s * 16;
        const float* xr0 = x + (size_t)(mt * 16 + g) * TOTAL_IN + kk + 2 * q;
        const float* xr1 = xr0 + 8 * TOTAL_IN;
        float2 v00 = *(const float2*)xr0;
        float2 v10 = *(const float2*)xr1;
        float2 v01 = *(const float2*)(xr0 + 8);
        float2 v11 = *(const float2*)(xr1 + 8);
        uint4 o;
        o.x = pack_bf2(v00.x, v00.y);   // a0: (g,   2q..2q+1)
        o.y = pack_bf2(v10.x, v10.y);   // a1: (g+8, ...)
        o.z = pack_bf2(v01.x, v01.y);   // a2: (g,   2q+8..)
        o.w = pack_bf2(v11.x, v11.y);   // a3: (g+8, 2q+8..)
        g_xfrag[i] = o;
    } else if (i - NXF < NWF2) {
        int j = i - NXF;
        int lane = j & 31, t = (j >> 5) & 15, nt = j >> 9;
        int g = lane >> 2, q = lane & 3;
        int k = t >> 1;                 // branch
        int s0 = (2 * t) & 3;           // even ks sub-step
        int kk = k * 64 + s0 * 16;
        const float* wr = w + (size_t)(nt * 8 + g) * TOTAL_IN + kk + 2 * q;
        float2 e0 = *(const float2*)wr;          // even ks, b0 (k rows 2q..)
        float2 e1 = *(const float2*)(wr + 8);    // even ks, b1 (k rows 2q+8..)
        float2 o0 = *(const float2*)(wr + 16);   // odd  ks, b0
        float2 o1 = *(const float2*)(wr + 24);   // odd  ks, b1
        uint4 o;
        o.x = pack_bf2(fmaxf(e0.x, 0.f), fmaxf(e0.y, 0.f));
        o.y = pack_bf2(fmaxf(e1.x, 0.f), fmaxf(e1.y, 0.f));
        o.z = pack_bf2(fmaxf(o0.x, 0.f), fmaxf(o0.y, 0.f));
        o.w = pack_bf2(fmaxf(o1.x, 0.f), fmaxf(o1.y, 0.f));
        g_wfrag2[j] = o;
    }
}

__device__ __forceinline__ void mma_bf16(float acc[4], const uint4& a,
                                         uint32_t b0, uint32_t b1) {
    asm volatile(
        "mma.sync.aligned.m16n8k16.row.col.f32.bf16.bf16.f32 "
        "{%0,%1,%2,%3}, {%4,%5,%6,%7}, {%8,%9}, {%0,%1,%2,%3};"
        : "+f"(acc[0]), "+f"(acc[1]), "+f"(acc[2]), "+f"(acc[3])
        : "r"(a.x), "r"(a.y), "r"(a.z), "r"(a.w), "r"(b0), "r"(b1));
}

// ---------------- main fused kernel ----------------
// CTA: 256 threads / 8 warps. Tile M=16 (batch) x N=64 (neurons).
// grid = (8192/64, 1024/16) = (128, 64)
#define ROWSTRIDE 580   // 64 pairs * 9 words + 4 pad (breaks 64*9≡0 mod 32)

__global__ __launch_bounds__(256)
void dendrite_main(const float* __restrict__ g_syn,
                   const float* __restrict__ plateaus,
                   const float* __restrict__ g_e,
                   const float* __restrict__ v_mem,
                   float* __restrict__ out)
{
    const float SYN_DECAY     = 0.99335550625f;  // exp(-0.1/15)
    const float PLATEAU_DECAY = 0.99875078085f;  // exp(-0.1/80)
    const float E_DECAY       = 0.98019867331f;  // exp(-0.1/5)

    __shared__ float s_acc[16 * ROWSTRIDE];      // 37,120 B

    const int tid = threadIdx.x;
    const int w = tid >> 5, lane = tid & 31;
    const int mt = blockIdx.y;
    const int nt8 = blockIdx.x * 8 + w;

    const uint4* xf  = g_xfrag  + (size_t)mt  * 1024 + lane;
    const uint4* wf2 = g_wfrag2 + (size_t)nt8 * 512  + lane;

    float acc[NB][4];
    #pragma unroll
    for (int k = 0; k < NB; k++)
        #pragma unroll
        for (int j = 0; j < 4; j++) acc[k][j] = 0.f;

    #pragma unroll
    for (int t = 0; t < 16; t++) {
        uint4 a0 = xf[(2 * t) * 32];
        uint4 a1 = xf[(2 * t + 1) * 32];
        uint4 bb = wf2[t * 32];
        mma_bf16(acc[t >> 1], a0, bb.x, bb.y);
        mma_bf16(acc[t >> 1], a1, bb.z, bb.w);
    }

    // ---- transpose acc into smem: pair p = b_local*64 + n_local ----
    {
        const int g = lane >> 2, q = lane & 3;
        #pragma unroll
        for (int j = 0; j < 4; j++) {
            const int bl = g + (j >> 1) * 8;
            const int nl = w * 8 + 2 * q + (j & 1);
            float* dst = s_acc + bl * ROWSTRIDE + nl * 9;
            #pragma unroll
            for (int k = 0; k < NB; k++) dst[k] = acc[k][j];
        }
    }
    __syncthreads();

    // ---- streaming epilogue: warp handles 128 consecutive pairs ----
    const int wbase = w * 128;
    #pragma unroll
    for (int j = 0; j < 4; j++) {
        const int p  = wbase + j * 32 + lane;
        const int bl = p >> 6, nl = p & 63;
        const int bg = mt * 16 + bl;
        const int ng = blockIdx.x * 64 + nl;
        const size_t idx = (size_t)bg * NN + ng;

        const float4* gp = (const float4*)(g_syn + idx * NB);
        const float4* pp = (const float4*)(plateaus + idx * NB);
        float4 gsA = gp[0], gsB = gp[1];
        float4 plA = pp[0], plB = pp[1];
        const float gev0 = g_e[idx];
        const float vm0  = v_mem[idx];

        const float* ap = s_acc + bl * ROWSTRIDE + nl * 9;
        float av[8];
        #pragma unroll
        for (int k = 0; k < NB; k++) av[k] = ap[k];

        float gs[8] = {gsA.x, gsA.y, gsA.z, gsA.w, gsB.x, gsB.y, gsB.z, gsB.w};
        float pl[8] = {plA.x, plA.y, plA.z, plA.w, plB.x, plB.y, plB.z, plB.w};

        float soma = 0.f;
        #pragma unroll
        for (int k = 0; k < NB; k++) {
            const float gv = fmaf(SYN_DECAY, gs[k], av[k]);
            const bool supra = gv > 0.3f;
            const float nmda = gv * (supra ? 3.0f : 0.8f);
            float pv = PLATEAU_DECAY * pl[k];
            if (supra) pv = fmaxf(pv, nmda);
            // 2*tanh(t/2) = 2*(1-e^-t)/(1+e^-t)
            const float e = __expf(-(nmda + pv));
            soma += 2.0f * __fdividef(1.0f - e, 1.0f + e);
        }
        const float ge_n = fmaf(E_DECAY, gev0, soma);
        float v = vm0 + 0.005f * (ge_n * (3.0f - vm0) - vm0);
        const float spk = (v >= 1.0f) ? 1.0f : 0.0f;
        if (v >= 1.0f) v = 0.0f;
        out[idx] = spk;
        out[(size_t)BATCH * NN + idx] = v;
    }
}

extern "C" void kernel_launch(void* const* d_in, const int* in_sizes, int n_in,
                              void* d_out, int out_size) {
    const float* inputs   = (const float*)d_in[0];
    const float* bw       = (const float*)d_in[1];
    const float* g_syn    = (const float*)d_in[2];
    const float* plateaus = (const float*)d_in[3];
    const float* g_e      = (const float*)d_in[4];
    const float* v_mem    = (const float*)d_in[5];
    float* out = (float*)d_out;

    const int NTOT = 64 * 32 * 32 + 1024 * 16 * 32;   // 589,824
    prep_kernel<<<(NTOT + 255) / 256, 256>>>(inputs, bw);

    dim3 grid(NN / 64, BATCH / 16);   // (128, 64)
    dendrite_main<<<grid, 256>>>(g_syn, plateaus, g_e, v_mem, out);
}